// round 3
// baseline (speedup 1.0000x reference)
#include <cuda_runtime.h>
#include <math.h>

#define N_ROWS 100000
#define IN_DIM 1024
#define DD 64
#define NQ 4
#define OUT_DIM 4

#define BR 128
#define KT 32
#define THREADS 256

// Scratch (no allocations allowed -> device globals)
__device__ float g_x[(size_t)N_ROWS * DD];       // projected features
__device__ float g_w[(size_t)NQ * N_ROWS];       // unnormalized softmax weights
__device__ float g_sum[NQ];
__device__ float g_latent[NQ * DD];
__device__ float g_Wq[DD * NQ];                  // W_k @ latent_q^T, [d][q]
__device__ float g_c[NQ];                        // latent_q . b_k

// ---------------- K0: fold W_k into the latent queries ----------------
__global__ void k0_precompute(const float* __restrict__ lq,
                              const float* __restrict__ W_k,
                              const float* __restrict__ b_k) {
    int t = threadIdx.x;
    if (t < DD * NQ) {
        int d = t >> 2, q = t & 3;
        float s = 0.f;
        #pragma unroll
        for (int j = 0; j < DD; j++) s = fmaf(W_k[d * DD + j], lq[q * DD + j], s);
        g_Wq[d * NQ + q] = s;
    }
    if (t < NQ) {
        float s = 0.f;
        #pragma unroll
        for (int j = 0; j < DD; j++) s = fmaf(lq[t * DD + j], b_k[j], s);
        g_c[t] = s;
    }
}

// ---------------- K1: main GEMM (x = patch @ W_proj + b) + score epilogue ----------------
__global__ __launch_bounds__(THREADS, 2)
void k1_main(const float* __restrict__ patch, const float* __restrict__ Wp,
             const float* __restrict__ bp, const float* __restrict__ Wg,
             const float* __restrict__ bg, float* __restrict__ out_scores) {
    __shared__ float As[BR][KT + 1];   // [row][k], pad -> conflict-free
    __shared__ float Bs[KT][DD];       // [k][col]

    const int tid = threadIdx.x;
    const int block_row = blockIdx.x * BR;
    const int tr = tid >> 4;           // 0..15 (8 rows each)
    const int tc = tid & 15;           // 0..15 (4 cols each)
    const int r0 = tr * 8;
    const int c0 = tc * 4;

    float acc[8][4];
    #pragma unroll
    for (int i = 0; i < 8; i++)
        #pragma unroll
        for (int j = 0; j < 4; j++) acc[i][j] = 0.f;

    for (int kt = 0; kt < IN_DIM; kt += KT) {
        // Load A tile: 128 rows x 32 k  (coalesced float4)
        #pragma unroll
        for (int l = 0; l < 4; l++) {
            int idx = tid + l * 256;
            int row = idx >> 3;
            int k4  = idx & 7;
            int grow = block_row + row;
            float4 v = make_float4(0.f, 0.f, 0.f, 0.f);
            if (grow < N_ROWS)
                v = *(const float4*)(patch + (size_t)grow * IN_DIM + kt + k4 * 4);
            As[row][k4 * 4 + 0] = v.x;
            As[row][k4 * 4 + 1] = v.y;
            As[row][k4 * 4 + 2] = v.z;
            As[row][k4 * 4 + 3] = v.w;
        }
        // Load B tile: 32 k x 64 cols
        #pragma unroll
        for (int l = 0; l < 2; l++) {
            int idx = tid + l * 256;
            int k  = idx >> 4;
            int c4 = idx & 15;
            float4 v = *(const float4*)(Wp + (size_t)(kt + k) * DD + c4 * 4);
            *(float4*)&Bs[k][c4 * 4] = v;
        }
        __syncthreads();

        #pragma unroll
        for (int k = 0; k < KT; k++) {
            float b[4];
            *(float4*)b = *(const float4*)&Bs[k][c0];
            float a[8];
            #pragma unroll
            for (int i = 0; i < 8; i++) a[i] = As[r0 + i][k];
            #pragma unroll
            for (int i = 0; i < 8; i++)
                #pragma unroll
                for (int j = 0; j < 4; j++)
                    acc[i][j] = fmaf(a[i], b[j], acc[i][j]);
        }
        __syncthreads();
    }

    // bias + store x tile to global scratch
    float bias[4];
    *(float4*)bias = *(const float4*)(bp + c0);
    #pragma unroll
    for (int i = 0; i < 8; i++) {
        int grow = block_row + r0 + i;
        if (grow < N_ROWS) {
            float4 v = make_float4(acc[i][0] + bias[0], acc[i][1] + bias[1],
                                   acc[i][2] + bias[2], acc[i][3] + bias[3]);
            *(float4*)(g_x + (size_t)grow * DD + c0) = v;
        }
    }
    __syncthreads();  // make g_x writes visible block-wide

    // Epilogue: gate + 4 scores per row (threads 0..127, one row each)
    if (tid < BR) {
        int grow = block_row + tid;
        if (grow < N_ROWS) {
            const float* xr = g_x + (size_t)grow * DD;
            float zg = bg[0];
            float dq[4] = {g_c[0], g_c[1], g_c[2], g_c[3]};
            #pragma unroll
            for (int d = 0; d < DD; d++) {
                float xv = xr[d];
                zg = fmaf(xv, Wg[d], zg);
                #pragma unroll
                for (int q = 0; q < NQ; q++)
                    dq[q] = fmaf(xv, g_Wq[d * NQ + q], dq[q]);
            }
            float gate = 1.f / (1.f + expf(-zg));
            float gs = gate * 0.125f;   // scale = 1/sqrt(64)
            #pragma unroll
            for (int q = 0; q < NQ; q++)
                out_scores[(size_t)q * N_ROWS + grow] = gs * dq[q];
        }
    }
}

// ---------------- K2: softmax reduce per query ----------------
__global__ void k2_softmax(const float* __restrict__ scores,
                           const unsigned char* __restrict__ mask) {
    const int q = blockIdx.x;
    const int tid = threadIdx.x;       // 256 threads
    __shared__ float red[256];

    if (tid < DD) g_latent[q * DD + tid] = 0.f;

    const float* s = scores + (size_t)q * N_ROWS;
    float m = -3.4e38f;
    for (int i = tid; i < N_ROWS; i += 256) {
        float v = mask[i] ? -3.4e38f : s[i];
        m = fmaxf(m, v);
    }
    red[tid] = m; __syncthreads();
    for (int off = 128; off > 0; off >>= 1) {
        if (tid < off) red[tid] = fmaxf(red[tid], red[tid + off]);
        __syncthreads();
    }
    m = red[0];
    __syncthreads();

    float tot = 0.f;
    for (int i = tid; i < N_ROWS; i += 256) {
        float e = mask[i] ? 0.f : expf(s[i] - m);
        g_w[(size_t)q * N_ROWS + i] = e;
        tot += e;
    }
    red[tid] = tot; __syncthreads();
    for (int off = 128; off > 0; off >>= 1) {
        if (tid < off) red[tid] += red[tid + off];
        __syncthreads();
    }
    if (tid == 0) g_sum[q] = red[0];
}

// ---------------- K3: latent[q][d] = sum_n w[q][n] * x[n][d] / sum[q] ----------------
__global__ void k3_latent() {
    const int tid = threadIdx.x;       // 256
    const int d = tid & 63;
    const int g = tid >> 6;            // 0..3 row-groups
    const int chunk = (N_ROWS + gridDim.x - 1) / gridDim.x;
    const int n0 = blockIdx.x * chunk;
    const int n1 = min(N_ROWS, n0 + chunk);

    float acc[NQ] = {0.f, 0.f, 0.f, 0.f};
    for (int n = n0 + g; n < n1; n += 4) {
        float xv = g_x[(size_t)n * DD + d];
        #pragma unroll
        for (int q = 0; q < NQ; q++) {
            float w = __ldg(&g_w[(size_t)q * N_ROWS + n]);  // broadcast across 64 lanes
            acc[q] = fmaf(w, xv, acc[q]);
        }
    }
    __shared__ float red[4][NQ][DD];
    #pragma unroll
    for (int q = 0; q < NQ; q++) red[g][q][d] = acc[q];
    __syncthreads();
    if (g == 0) {
        #pragma unroll
        for (int q = 0; q < NQ; q++) {
            float s = red[0][q][d] + red[1][q][d] + red[2][q][d] + red[3][q][d];
            atomicAdd(&g_latent[q * DD + d], s / g_sum[q]);
        }
    }
}

// ---------------- K4: latent -> FC(relu) -> logits ----------------
__global__ void k4_final(const float* __restrict__ W_fc, const float* __restrict__ b_fc,
                         const float* __restrict__ W_out, const float* __restrict__ b_out,
                         float* __restrict__ logits) {
    __shared__ float v[NQ * DD];
    __shared__ float h[DD];
    const int tid = threadIdx.x;       // 256
    v[tid] = g_latent[tid];
    __syncthreads();
    if (tid < DD) {
        float s = b_fc[tid];
        #pragma unroll 8
        for (int i = 0; i < NQ * DD; i++)
            s = fmaf(v[i], W_fc[i * DD + tid], s);
        h[tid] = fmaxf(s, 0.f);
    }
    __syncthreads();
    if (tid < OUT_DIM) {
        float s = b_out[tid];
        #pragma unroll
        for (int j = 0; j < DD; j++)
            s = fmaf(h[j], W_out[j * OUT_DIM + tid], s);
        logits[tid] = s;
    }
}

extern "C" void kernel_launch(void* const* d_in, const int* in_sizes, int n_in,
                              void* d_out, int out_size) {
    const float*         patch  = (const float*)d_in[0];
    const unsigned char* mask   = (const unsigned char*)d_in[1];
    const float*         lq     = (const float*)d_in[2];
    const float*         W_proj = (const float*)d_in[3];
    const float*         b_proj = (const float*)d_in[4];
    const float*         W_k    = (const float*)d_in[5];
    const float*         b_k    = (const float*)d_in[6];
    const float*         W_gate = (const float*)d_in[7];
    const float*         b_gate = (const float*)d_in[8];
    const float*         W_fc   = (const float*)d_in[9];
    const float*         b_fc   = (const float*)d_in[10];
    const float*         W_out  = (const float*)d_in[11];
    const float*         b_out  = (const float*)d_in[12];

    float* out     = (float*)d_out;
    float* logits  = out;          // 4 floats
    float* scores  = out + 4;      // A_out: [4, 100000]

    k0_precompute<<<1, 256>>>(lq, W_k, b_k);
    k1_main<<<(N_ROWS + BR - 1) / BR, THREADS>>>(patch, W_proj, b_proj, W_gate, b_gate, scores);
    k2_softmax<<<NQ, 256>>>(scores, mask);
    k3_latent<<<250, 256>>>();
    k4_final<<<1, 256>>>(W_fc, b_fc, W_out, b_out, logits);
}

// round 4
// speedup vs baseline: 1.9440x; 1.9440x over previous
#include <cuda_runtime.h>
#include <math.h>

#define N_ROWS 100000
#define IN_DIM 1024
#define DD 64
#define NQ 4
#define OUT_DIM 4

#define BR 128
#define KT 16
#define THREADS 256

// Scratch (no allocations allowed -> device globals)
__device__ float g_x[(size_t)N_ROWS * DD];       // projected features
__device__ float g_w[(size_t)NQ * N_ROWS];       // unnormalized softmax weights
__device__ float g_sum[NQ];
__device__ float g_latent[NQ * DD];
__device__ float g_Wq[DD * NQ];                  // W_k @ latent_q^T, [d][q]
__device__ float g_c[NQ];                        // latent_q . b_k

// ---- helpers ----
__device__ __forceinline__ unsigned f2tf(float x) {
    unsigned r;
    asm("cvt.rna.tf32.f32 %0, %1;" : "=r"(r) : "f"(x));
    return r;
}

__device__ __forceinline__ void mma_tf32(float* c, const unsigned* a, const unsigned* b) {
    asm volatile(
        "mma.sync.aligned.m16n8k8.row.col.f32.tf32.tf32.f32 "
        "{%0,%1,%2,%3}, {%4,%5,%6,%7}, {%8,%9}, {%0,%1,%2,%3};"
        : "+f"(c[0]), "+f"(c[1]), "+f"(c[2]), "+f"(c[3])
        : "r"(a[0]), "r"(a[1]), "r"(a[2]), "r"(a[3]),
          "r"(b[0]), "r"(b[1]));
}

// ---------------- K0: fold W_k into latent queries; zero accumulators ----------------
__global__ void k0_precompute(const float* __restrict__ lq,
                              const float* __restrict__ W_k,
                              const float* __restrict__ b_k) {
    int t = threadIdx.x;
    if (t < DD * NQ) {
        int d = t >> 2, q = t & 3;
        float s = 0.f;
        #pragma unroll
        for (int j = 0; j < DD; j++) s = fmaf(W_k[d * DD + j], lq[q * DD + j], s);
        g_Wq[d * NQ + q] = s;
    }
    if (t < NQ) {
        float s = 0.f;
        #pragma unroll
        for (int j = 0; j < DD; j++) s = fmaf(lq[t * DD + j], b_k[j], s);
        g_c[t] = s;
        g_sum[t] = 0.f;
    }
    if (t < NQ * DD) g_latent[t] = 0.f;
}

// ---------------- K1: tf32 MMA GEMM + fused gate/score/exp epilogue ----------------
// x = patch @ W_proj + b_proj  (128x64 tile per CTA)
// warp layout: 8 warps = 4 (M, 32 rows) x 2 (N, 32 cols); warp tile 32x32
// per warp: 2 m16-tiles x 4 n8-tiles of m16n8k8
__global__ __launch_bounds__(THREADS)
void k1_mma(const float* __restrict__ patch, const float* __restrict__ Wp,
            const float* __restrict__ bp, const float* __restrict__ Wg,
            const float* __restrict__ bg, const unsigned char* __restrict__ mask,
            float* __restrict__ out_scores) {
    __shared__ unsigned As[2][BR][20];   // [buf][row][k], stride 20 -> conflict-free frag loads
    __shared__ unsigned Bs[2][KT][72];   // [buf][k][col], stride 72 -> conflict-free frag loads
    __shared__ float psum[NQ];

    const int tid = threadIdx.x;
    const int lane = tid & 31;
    const int wid = tid >> 5;
    const int wm = wid & 3;             // row slice 0..3
    const int wn = wid >> 2;            // col slice 0..1
    const int g = lane >> 2;            // 0..7
    const int t = lane & 3;             // 0..3
    const int block_row = blockIdx.x * BR;

    if (tid < NQ) psum[tid] = 0.f;

    float acc[2][4][4];
    #pragma unroll
    for (int mt = 0; mt < 2; mt++)
        #pragma unroll
        for (int nt = 0; nt < 4; nt++)
            #pragma unroll
            for (int i = 0; i < 4; i++) acc[mt][nt][i] = 0.f;

    // A-tile load indices (2 float4 per thread), B-tile (1 float4 per thread)
    const int a_row0 = tid >> 2;            // idx = tid       -> rows 0..63
    const int a_row1 = (tid + 256) >> 2;    //                -> rows 64..127
    const int a_k4 = tid & 3;
    const int b_k = tid >> 4;
    const int b_c4 = tid & 15;

    // prologue: load tile 0 into buf 0
    {
        float4 va0 = make_float4(0.f, 0.f, 0.f, 0.f), va1 = va0;
        int gr0 = block_row + a_row0, gr1 = block_row + a_row1;
        if (gr0 < N_ROWS) va0 = *(const float4*)(patch + (size_t)gr0 * IN_DIM + a_k4 * 4);
        if (gr1 < N_ROWS) va1 = *(const float4*)(patch + (size_t)gr1 * IN_DIM + a_k4 * 4);
        float4 vb = *(const float4*)(Wp + (size_t)b_k * DD + b_c4 * 4);
        As[0][a_row0][a_k4 * 4 + 0] = f2tf(va0.x); As[0][a_row0][a_k4 * 4 + 1] = f2tf(va0.y);
        As[0][a_row0][a_k4 * 4 + 2] = f2tf(va0.z); As[0][a_row0][a_k4 * 4 + 3] = f2tf(va0.w);
        As[0][a_row1][a_k4 * 4 + 0] = f2tf(va1.x); As[0][a_row1][a_k4 * 4 + 1] = f2tf(va1.y);
        As[0][a_row1][a_k4 * 4 + 2] = f2tf(va1.z); As[0][a_row1][a_k4 * 4 + 3] = f2tf(va1.w);
        Bs[0][b_k][b_c4 * 4 + 0] = f2tf(vb.x); Bs[0][b_k][b_c4 * 4 + 1] = f2tf(vb.y);
        Bs[0][b_k][b_c4 * 4 + 2] = f2tf(vb.z); Bs[0][b_k][b_c4 * 4 + 3] = f2tf(vb.w);
    }
    __syncthreads();

    const int NTILES = IN_DIM / KT;  // 64
    for (int it = 0; it < NTILES; it++) {
        const int buf = it & 1;
        const int nxt = buf ^ 1;

        // issue next-tile global loads early
        float4 va0, va1, vb;
        bool have_next = (it + 1 < NTILES);
        if (have_next) {
            int kt = (it + 1) * KT;
            va0 = make_float4(0.f, 0.f, 0.f, 0.f); va1 = va0;
            int gr0 = block_row + a_row0, gr1 = block_row + a_row1;
            if (gr0 < N_ROWS) va0 = *(const float4*)(patch + (size_t)gr0 * IN_DIM + kt + a_k4 * 4);
            if (gr1 < N_ROWS) va1 = *(const float4*)(patch + (size_t)gr1 * IN_DIM + kt + a_k4 * 4);
            vb = *(const float4*)(Wp + (size_t)(kt + b_k) * DD + b_c4 * 4);
        }

        // compute on current buffer: 2 k8-steps
        #pragma unroll
        for (int ks = 0; ks < 2; ks++) {
            const int kb = ks * 8;
            unsigned a[2][4];
            #pragma unroll
            for (int mt = 0; mt < 2; mt++) {
                int r0 = wm * 32 + mt * 16;
                a[mt][0] = As[buf][r0 + g][kb + t];
                a[mt][1] = As[buf][r0 + g + 8][kb + t];
                a[mt][2] = As[buf][r0 + g][kb + t + 4];
                a[mt][3] = As[buf][r0 + g + 8][kb + t + 4];
            }
            unsigned b[4][2];
            #pragma unroll
            for (int nt = 0; nt < 4; nt++) {
                int c0 = wn * 32 + nt * 8;
                b[nt][0] = Bs[buf][kb + t][c0 + g];
                b[nt][1] = Bs[buf][kb + t + 4][c0 + g];
            }
            #pragma unroll
            for (int mt = 0; mt < 2; mt++)
                #pragma unroll
                for (int nt = 0; nt < 4; nt++)
                    mma_tf32(acc[mt][nt], a[mt], b[nt]);
        }

        if (have_next) {
            As[nxt][a_row0][a_k4 * 4 + 0] = f2tf(va0.x); As[nxt][a_row0][a_k4 * 4 + 1] = f2tf(va0.y);
            As[nxt][a_row0][a_k4 * 4 + 2] = f2tf(va0.z); As[nxt][a_row0][a_k4 * 4 + 3] = f2tf(va0.w);
            As[nxt][a_row1][a_k4 * 4 + 0] = f2tf(va1.x); As[nxt][a_row1][a_k4 * 4 + 1] = f2tf(va1.y);
            As[nxt][a_row1][a_k4 * 4 + 2] = f2tf(va1.z); As[nxt][a_row1][a_k4 * 4 + 3] = f2tf(va1.w);
            Bs[nxt][b_k][b_c4 * 4 + 0] = f2tf(vb.x); Bs[nxt][b_k][b_c4 * 4 + 1] = f2tf(vb.y);
            Bs[nxt][b_k][b_c4 * 4 + 2] = f2tf(vb.z); Bs[nxt][b_k][b_c4 * 4 + 3] = f2tf(vb.w);
        }
        __syncthreads();
    }

    // write x tile (with bias) to global scratch
    #pragma unroll
    for (int mt = 0; mt < 2; mt++) {
        #pragma unroll
        for (int nt = 0; nt < 4; nt++) {
            int col = wn * 32 + nt * 8 + t * 2;
            float b0 = bp[col], b1 = bp[col + 1];
            int row = block_row + wm * 32 + mt * 16 + g;
            if (row < N_ROWS) {
                float2 v = make_float2(acc[mt][nt][0] + b0, acc[mt][nt][1] + b1);
                *(float2*)(g_x + (size_t)row * DD + col) = v;
            }
            int row2 = row + 8;
            if (row2 < N_ROWS) {
                float2 v = make_float2(acc[mt][nt][2] + b0, acc[mt][nt][3] + b1);
                *(float2*)(g_x + (size_t)row2 * DD + col) = v;
            }
        }
    }
    __syncthreads();   // block-level visibility of g_x writes (global ordered by barrier)

    // fused epilogue: gate + 4 scores + exp weights + partial softmax sums
    if (tid < BR) {
        int grow = block_row + tid;
        if (grow < N_ROWS) {
            const float* xr = g_x + (size_t)grow * DD;
            float zg = bg[0];
            float dq[4] = {g_c[0], g_c[1], g_c[2], g_c[3]};
            #pragma unroll
            for (int d = 0; d < DD; d++) {
                float xv = xr[d];
                zg = fmaf(xv, Wg[d], zg);
                #pragma unroll
                for (int q = 0; q < NQ; q++)
                    dq[q] = fmaf(xv, g_Wq[d * NQ + q], dq[q]);
            }
            float gate = 1.f / (1.f + expf(-zg));
            float gs = gate * 0.125f;                 // scale = 1/sqrt(64)
            bool valid = (mask[grow] == 0);
            #pragma unroll
            for (int q = 0; q < NQ; q++) {
                float s = gs * dq[q];
                out_scores[(size_t)q * N_ROWS + grow] = s;
                float w = valid ? expf(s) : 0.f;      // softmax is shift-invariant; scores are O(1)
                g_w[(size_t)q * N_ROWS + grow] = w;
                atomicAdd(&psum[q], w);
            }
        }
    }
    __syncthreads();
    if (tid < NQ) atomicAdd(&g_sum[tid], psum[tid]);
}

// ---------------- K3: latent[q][d] = sum_n w[q][n] * x[n][d] / sum[q] ----------------
__global__ void k3_latent() {
    const int tid = threadIdx.x;       // 256
    const int d = tid & 63;
    const int g = tid >> 6;            // 0..3 row-groups
    const int chunk = (N_ROWS + gridDim.x - 1) / gridDim.x;
    const int n0 = blockIdx.x * chunk;
    const int n1 = min(N_ROWS, n0 + chunk);

    float acc[NQ] = {0.f, 0.f, 0.f, 0.f};
    for (int i = n0; i < n1; i += 16) {
        int nb = i + g * 4;
        #pragma unroll
        for (int u = 0; u < 4; u++) {
            int n = nb + u;
            if (n < n1) {
                float xv = g_x[(size_t)n * DD + d];
                #pragma unroll
                for (int q = 0; q < NQ; q++)
                    acc[q] = fmaf(__ldg(&g_w[(size_t)q * N_ROWS + n]), xv, acc[q]);
            }
        }
    }
    __shared__ float red[4][NQ][DD];
    #pragma unroll
    for (int q = 0; q < NQ; q++) red[g][q][d] = acc[q];
    __syncthreads();
    if (g == 0) {
        #pragma unroll
        for (int q = 0; q < NQ; q++) {
            float s = red[0][q][d] + red[1][q][d] + red[2][q][d] + red[3][q][d];
            atomicAdd(&g_latent[q * DD + d], s / g_sum[q]);
        }
    }
}

// ---------------- K4: latent -> FC(relu) -> logits ----------------
__global__ void k4_final(const float* __restrict__ W_fc, const float* __restrict__ b_fc,
                         const float* __restrict__ W_out, const float* __restrict__ b_out,
                         float* __restrict__ logits) {
    __shared__ float v[NQ * DD];
    __shared__ float h[DD];
    const int tid = threadIdx.x;       // 256
    v[tid] = g_latent[tid];
    __syncthreads();
    if (tid < DD) {
        float s = b_fc[tid];
        #pragma unroll 8
        for (int i = 0; i < NQ * DD; i++)
            s = fmaf(v[i], W_fc[i * DD + tid], s);
        h[tid] = fmaxf(s, 0.f);
    }
    __syncthreads();
    if (tid < OUT_DIM) {
        float s = b_out[tid];
        #pragma unroll
        for (int j = 0; j < DD; j++)
            s = fmaf(h[j], W_out[j * OUT_DIM + tid], s);
        logits[tid] = s;
    }
}

extern "C" void kernel_launch(void* const* d_in, const int* in_sizes, int n_in,
                              void* d_out, int out_size) {
    const float*         patch  = (const float*)d_in[0];
    const unsigned char* mask   = (const unsigned char*)d_in[1];
    const float*         lq     = (const float*)d_in[2];
    const float*         W_proj = (const float*)d_in[3];
    const float*         b_proj = (const float*)d_in[4];
    const float*         W_k    = (const float*)d_in[5];
    const float*         b_k    = (const float*)d_in[6];
    const float*         W_gate = (const float*)d_in[7];
    const float*         b_gate = (const float*)d_in[8];
    const float*         W_fc   = (const float*)d_in[9];
    const float*         b_fc   = (const float*)d_in[10];
    const float*         W_out  = (const float*)d_in[11];
    const float*         b_out  = (const float*)d_in[12];

    float* out     = (float*)d_out;
    float* logits  = out;          // 4 floats
    float* scores  = out + 4;      // A_out: [4, 100000]

    k0_precompute<<<1, 256>>>(lq, W_k, b_k);
    k1_mma<<<(N_ROWS + BR - 1) / BR, THREADS>>>(patch, W_proj, b_proj, W_gate, b_gate, mask, scores);
    k3_latent<<<400, 256>>>();
    k4_final<<<1, 256>>>(W_fc, b_fc, W_out, b_out, logits);
}

// round 5
// speedup vs baseline: 2.7681x; 1.4239x over previous
#include <cuda_runtime.h>
#include <math.h>

#define N_ROWS 100000
#define IN_DIM 1024
#define DD 64
#define NQ 4
#define OUT_DIM 4

#define BR 128
#define KT 16
#define THREADS 256
#define STAGES 4

// dynamic smem layout (floats)
#define AS_STRIDE 20
#define AS_STAGE (BR * AS_STRIDE)          // 2560
#define BS_STRIDE 72
#define BS_STAGE (KT * BS_STRIDE)          // 1152
#define XS_STRIDE 65
#define AS_OFF 0
#define BS_OFF (STAGES * AS_STAGE)         // 10240
#define XS_OFF (BS_OFF + STAGES * BS_STAGE)// 14848
#define SMEM_FLOATS (XS_OFF + BR * XS_STRIDE)   // 23168
#define SMEM_BYTES (SMEM_FLOATS * 4)            // 92672

// Scratch (no allocations allowed -> device globals)
__device__ float g_x[(size_t)N_ROWS * DD];       // projected features
__device__ float g_w[(size_t)NQ * N_ROWS];       // unnormalized softmax weights
__device__ float g_sum[NQ];
__device__ float g_latent[NQ * DD];
__device__ float g_Wq[DD * NQ];                  // W_k @ latent_q^T, [d][q]
__device__ float g_c[NQ];                        // latent_q . b_k

// ---- helpers ----
__device__ __forceinline__ unsigned f2tf(float x) {
    unsigned r;
    asm("cvt.rna.tf32.f32 %0, %1;" : "=r"(r) : "f"(x));
    return r;
}

__device__ __forceinline__ void mma_tf32(float* c, const unsigned* a, const unsigned* b) {
    asm volatile(
        "mma.sync.aligned.m16n8k8.row.col.f32.tf32.tf32.f32 "
        "{%0,%1,%2,%3}, {%4,%5,%6,%7}, {%8,%9}, {%0,%1,%2,%3};"
        : "+f"(c[0]), "+f"(c[1]), "+f"(c[2]), "+f"(c[3])
        : "r"(a[0]), "r"(a[1]), "r"(a[2]), "r"(a[3]),
          "r"(b[0]), "r"(b[1]));
}

__device__ __forceinline__ void cp16(unsigned dst, const void* src) {
    asm volatile("cp.async.cg.shared.global [%0], [%1], 16;" :: "r"(dst), "l"(src));
}

// ---------------- K0: fold W_k into latent queries; zero accumulators ----------------
__global__ void k0_precompute(const float* __restrict__ lq,
                              const float* __restrict__ W_k,
                              const float* __restrict__ b_k) {
    int t = threadIdx.x;
    if (t < DD * NQ) {
        int d = t >> 2, q = t & 3;
        float s = 0.f;
        #pragma unroll
        for (int j = 0; j < DD; j++) s = fmaf(W_k[d * DD + j], lq[q * DD + j], s);
        g_Wq[d * NQ + q] = s;
    }
    if (t < NQ) {
        float s = 0.f;
        #pragma unroll
        for (int j = 0; j < DD; j++) s = fmaf(lq[t * DD + j], b_k[j], s);
        g_c[t] = s;
        g_sum[t] = 0.f;
    }
    if (t < NQ * DD) g_latent[t] = 0.f;
}

// ---------------- K1: tf32 MMA GEMM (4-stage cp.async) + fused epilogue ----------------
__global__ __launch_bounds__(THREADS, 2)
void k1_mma(const float* __restrict__ patch, const float* __restrict__ Wp,
            const float* __restrict__ bp, const float* __restrict__ Wg,
            const float* __restrict__ bg, const unsigned char* __restrict__ mask,
            float* __restrict__ out_scores) {
    extern __shared__ float smem[];
    float* As = smem + AS_OFF;
    float* Bs = smem + BS_OFF;
    float* xs = smem + XS_OFF;
    __shared__ float psum[NQ];

    const int tid = threadIdx.x;
    const int lane = tid & 31;
    const int wid = tid >> 5;
    const int wm = wid & 3;             // row slice 0..3
    const int wn = wid >> 2;            // col slice 0..1
    const int g = lane >> 2;            // 0..7
    const int t = lane & 3;             // 0..3
    const int block_row = blockIdx.x * BR;

    if (tid < NQ) psum[tid] = 0.f;

    const unsigned smem_base = (unsigned)__cvta_generic_to_shared(smem);
    const unsigned as_base = smem_base + AS_OFF * 4;
    const unsigned bs_base = smem_base + BS_OFF * 4;

    // per-thread cp.async indices
    const int a_row0 = tid >> 2;           // chunk tid      -> rows 0..63
    const int a_row1 = (tid + 256) >> 2;   // chunk tid+256  -> rows 64..127
    const int a_c = tid & 3;               // 16B chunk within row
    const int b_k = tid >> 4;
    const int b_c = tid & 15;
    const size_t a_src0 = (size_t)min(block_row + a_row0, N_ROWS - 1) * IN_DIM + a_c * 4;
    const size_t a_src1 = (size_t)min(block_row + a_row1, N_ROWS - 1) * IN_DIM + a_c * 4;

    float acc[2][4][4];
    #pragma unroll
    for (int mt = 0; mt < 2; mt++)
        #pragma unroll
        for (int nt = 0; nt < 4; nt++)
            #pragma unroll
            for (int i = 0; i < 4; i++) acc[mt][nt][i] = 0.f;

    const int NTILES = IN_DIM / KT;  // 64

    // prologue: stages 0..2
    #pragma unroll
    for (int s = 0; s < STAGES - 1; s++) {
        int kt = s * KT;
        cp16(as_base + (s * AS_STAGE + a_row0 * AS_STRIDE + a_c * 4) * 4, patch + a_src0 + kt);
        cp16(as_base + (s * AS_STAGE + a_row1 * AS_STRIDE + a_c * 4) * 4, patch + a_src1 + kt);
        cp16(bs_base + (s * BS_STAGE + b_k * BS_STRIDE + b_c * 4) * 4,
             Wp + (size_t)(kt + b_k) * DD + b_c * 4);
        asm volatile("cp.async.commit_group;");
    }

    for (int it = 0; it < NTILES; it++) {
        asm volatile("cp.async.wait_group 2;");
        __syncthreads();

        if (it + STAGES - 1 < NTILES) {
            int s = (it + STAGES - 1) & (STAGES - 1);
            int kt = (it + STAGES - 1) * KT;
            cp16(as_base + (s * AS_STAGE + a_row0 * AS_STRIDE + a_c * 4) * 4, patch + a_src0 + kt);
            cp16(as_base + (s * AS_STAGE + a_row1 * AS_STRIDE + a_c * 4) * 4, patch + a_src1 + kt);
            cp16(bs_base + (s * BS_STAGE + b_k * BS_STRIDE + b_c * 4) * 4,
                 Wp + (size_t)(kt + b_k) * DD + b_c * 4);
        }
        asm volatile("cp.async.commit_group;");

        const float* Ab = As + (it & (STAGES - 1)) * AS_STAGE;
        const float* Bb = Bs + (it & (STAGES - 1)) * BS_STAGE;

        #pragma unroll
        for (int ks = 0; ks < 2; ks++) {
            const int kb = ks * 8;
            unsigned a[2][4];
            #pragma unroll
            for (int mt = 0; mt < 2; mt++) {
                int r0 = wm * 32 + mt * 16;
                a[mt][0] = f2tf(Ab[(r0 + g) * AS_STRIDE + kb + t]);
                a[mt][1] = f2tf(Ab[(r0 + g + 8) * AS_STRIDE + kb + t]);
                a[mt][2] = f2tf(Ab[(r0 + g) * AS_STRIDE + kb + t + 4]);
                a[mt][3] = f2tf(Ab[(r0 + g + 8) * AS_STRIDE + kb + t + 4]);
            }
            unsigned b[4][2];
            #pragma unroll
            for (int nt = 0; nt < 4; nt++) {
                int c0 = wn * 32 + nt * 8;
                b[nt][0] = f2tf(Bb[(kb + t) * BS_STRIDE + c0 + g]);
                b[nt][1] = f2tf(Bb[(kb + t + 4) * BS_STRIDE + c0 + g]);
            }
            #pragma unroll
            for (int mt = 0; mt < 2; mt++)
                #pragma unroll
                for (int nt = 0; nt < 4; nt++)
                    mma_tf32(acc[mt][nt], a[mt], b[nt]);
        }
    }

    // store x tile: registers -> smem staging + global scratch (with bias)
    #pragma unroll
    for (int mt = 0; mt < 2; mt++) {
        #pragma unroll
        for (int nt = 0; nt < 4; nt++) {
            int col = wn * 32 + nt * 8 + t * 2;
            float b0 = bp[col], b1 = bp[col + 1];
            int lrow = wm * 32 + mt * 16 + g;
            int row = block_row + lrow;
            float v0 = acc[mt][nt][0] + b0, v1 = acc[mt][nt][1] + b1;
            xs[lrow * XS_STRIDE + col] = v0;
            xs[lrow * XS_STRIDE + col + 1] = v1;
            if (row < N_ROWS)
                *(float2*)(g_x + (size_t)row * DD + col) = make_float2(v0, v1);
            float v2 = acc[mt][nt][2] + b0, v3 = acc[mt][nt][3] + b1;
            xs[(lrow + 8) * XS_STRIDE + col] = v2;
            xs[(lrow + 8) * XS_STRIDE + col + 1] = v3;
            if (row + 8 < N_ROWS)
                *(float2*)(g_x + (size_t)(row + 8) * DD + col) = make_float2(v2, v3);
        }
    }
    __syncthreads();

    // fused epilogue: gate + 4 scores + exp weights + partial softmax sums
    if (tid < BR) {
        int grow = block_row + tid;
        bool in_range = (grow < N_ROWS);
        float zg = bg[0];
        float dq[4] = {g_c[0], g_c[1], g_c[2], g_c[3]};
        const float* xr = xs + tid * XS_STRIDE;
        #pragma unroll
        for (int d = 0; d < DD; d++) {
            float xv = xr[d];
            zg = fmaf(xv, Wg[d], zg);
            #pragma unroll
            for (int q = 0; q < NQ; q++)
                dq[q] = fmaf(xv, g_Wq[d * NQ + q], dq[q]);
        }
        float gate = 1.f / (1.f + expf(-zg));
        float gs = gate * 0.125f;                 // scale = 1/sqrt(64)
        bool valid = in_range && (mask[min(grow, N_ROWS - 1)] == 0);
        float w[4];
        #pragma unroll
        for (int q = 0; q < NQ; q++) {
            float s = gs * dq[q];
            if (in_range) out_scores[(size_t)q * N_ROWS + grow] = s;
            w[q] = valid ? expf(s) : 0.f;          // softmax shift-invariant; scores O(1)
            if (in_range) g_w[(size_t)q * N_ROWS + grow] = w[q];
        }
        // warp-level reduce of w before shared atomics
        #pragma unroll
        for (int q = 0; q < NQ; q++) {
            float v = w[q];
            #pragma unroll
            for (int off = 16; off > 0; off >>= 1)
                v += __shfl_xor_sync(0xffffffffu, v, off);
            if (lane == 0) atomicAdd(&psum[q], v);
        }
    }
    __syncthreads();
    if (tid < NQ) atomicAdd(&g_sum[tid], psum[tid]);
}

// ---------------- K3: latent[q][d] = sum_n w[q][n] * x[n][d] / sum[q] ----------------
// grid = 625 -> each block handles exactly 160 rows; 4 groups of 64 threads, 40 iters each
__global__ void k3_latent() {
    const int tid = threadIdx.x;       // 256
    const int d = tid & 63;
    const int g = tid >> 6;            // 0..3 row-groups
    const int n0 = blockIdx.x * 160;

    float acc[NQ] = {0.f, 0.f, 0.f, 0.f};
    #pragma unroll 8
    for (int i = 0; i < 40; i++) {
        int n = n0 + g + i * 4;
        float xv = g_x[(size_t)n * DD + d];
        #pragma unroll
        for (int q = 0; q < NQ; q++)
            acc[q] = fmaf(__ldg(&g_w[(size_t)q * N_ROWS + n]), xv, acc[q]);
    }
    __shared__ float red[4][NQ][DD];
    #pragma unroll
    for (int q = 0; q < NQ; q++) red[g][q][d] = acc[q];
    __syncthreads();
    if (g == 0) {
        #pragma unroll
        for (int q = 0; q < NQ; q++) {
            float s = red[0][q][d] + red[1][q][d] + red[2][q][d] + red[3][q][d];
            atomicAdd(&g_latent[q * DD + d], s / g_sum[q]);
        }
    }
}

// ---------------- K4: latent -> FC(relu) -> logits ----------------
__global__ void k4_final(const float* __restrict__ W_fc, const float* __restrict__ b_fc,
                         const float* __restrict__ W_out, const float* __restrict__ b_out,
                         float* __restrict__ logits) {
    __shared__ float v[NQ * DD];
    __shared__ float hpart[4][DD];
    __shared__ float h[DD];
    const int tid = threadIdx.x;       // 256
    v[tid] = g_latent[tid];
    __syncthreads();
    const int g = tid >> 6;            // 0..3: which 64-row slab of W_fc
    const int col = tid & 63;
    {
        float s = 0.f;
        const float* wp = W_fc + (size_t)(g * 64) * DD + col;
        const float* vp = v + g * 64;
        #pragma unroll 8
        for (int i = 0; i < 64; i++)
            s = fmaf(vp[i], wp[(size_t)i * DD], s);
        hpart[g][col] = s;
    }
    __syncthreads();
    if (tid < DD) {
        float s = hpart[0][tid] + hpart[1][tid] + hpart[2][tid] + hpart[3][tid] + b_fc[tid];
        h[tid] = fmaxf(s, 0.f);
    }
    __syncthreads();
    if (tid < OUT_DIM) {
        float s = b_out[tid];
        #pragma unroll
        for (int j = 0; j < DD; j++)
            s = fmaf(h[j], W_out[j * OUT_DIM + tid], s);
        logits[tid] = s;
    }
}

extern "C" void kernel_launch(void* const* d_in, const int* in_sizes, int n_in,
                              void* d_out, int out_size) {
    const float*         patch  = (const float*)d_in[0];
    const unsigned char* mask   = (const unsigned char*)d_in[1];
    const float*         lq     = (const float*)d_in[2];
    const float*         W_proj = (const float*)d_in[3];
    const float*         b_proj = (const float*)d_in[4];
    const float*         W_k    = (const float*)d_in[5];
    const float*         b_k    = (const float*)d_in[6];
    const float*         W_gate = (const float*)d_in[7];
    const float*         b_gate = (const float*)d_in[8];
    const float*         W_fc   = (const float*)d_in[9];
    const float*         b_fc   = (const float*)d_in[10];
    const float*         W_out  = (const float*)d_in[11];
    const float*         b_out  = (const float*)d_in[12];

    float* out     = (float*)d_out;
    float* logits  = out;          // 4 floats
    float* scores  = out + 4;      // A_out: [4, 100000]

    cudaFuncSetAttribute(k1_mma, cudaFuncAttributeMaxDynamicSharedMemorySize, SMEM_BYTES);

    k0_precompute<<<1, 256>>>(lq, W_k, b_k);
    k1_mma<<<(N_ROWS + BR - 1) / BR, THREADS, SMEM_BYTES>>>(patch, W_proj, b_proj,
                                                            W_gate, b_gate, mask, scores);
    k3_latent<<<625, 256>>>();
    k4_final<<<1, 256>>>(W_fc, b_fc, W_out, b_out, logits);
}

// round 6
// speedup vs baseline: 2.8393x; 1.0257x over previous
#include <cuda_runtime.h>
#include <math.h>

#define N_ROWS 100000
#define IN_DIM 1024
#define DD 64
#define NQ 4
#define OUT_DIM 4

#define BR 128
#define KT 16
#define THREADS 256
#define STAGES 4

// compensate 2x tf32 truncation bias (each operand mean rel err -2^-12)
#define BSCALE 1.00048828125f

// dynamic smem layout (floats)
#define AS_STRIDE 20
#define AS_STAGE (BR * AS_STRIDE)          // 2560
#define BS_STRIDE 72
#define BS_STAGE (KT * BS_STRIDE)          // 1152
#define XS_STRIDE 65
#define AS_OFF 0
#define BS_OFF (STAGES * AS_STAGE)         // 10240
#define XS_OFF (BS_OFF + STAGES * BS_STAGE)// 14848
#define SMEM_FLOATS (XS_OFF + BR * XS_STRIDE)   // 23168
#define SMEM_BYTES (SMEM_FLOATS * 4)            // 92672

#define K3_BLOCKS 1250

// Scratch (no allocations allowed -> device globals)
__device__ float g_x[(size_t)N_ROWS * DD];       // projected features
__device__ float g_w[(size_t)NQ * N_ROWS];       // unnormalized softmax weights
__device__ float g_sum[NQ];
__device__ float g_latent[NQ * DD];
__device__ float g_Wq[DD * NQ];                  // W_k @ latent_q^T, [d][q]
__device__ float g_c[NQ];                        // latent_q . b_k
__device__ float g_Bp[IN_DIM * DD];              // W_proj * BSCALE
__device__ unsigned g_ticket;

// ---- helpers ----
__device__ __forceinline__ void mma_tf32(float* c, const unsigned* a, const unsigned* b) {
    asm volatile(
        "mma.sync.aligned.m16n8k8.row.col.f32.tf32.tf32.f32 "
        "{%0,%1,%2,%3}, {%4,%5,%6,%7}, {%8,%9}, {%0,%1,%2,%3};"
        : "+f"(c[0]), "+f"(c[1]), "+f"(c[2]), "+f"(c[3])
        : "r"(a[0]), "r"(a[1]), "r"(a[2]), "r"(a[3]),
          "r"(b[0]), "r"(b[1]));
}

__device__ __forceinline__ void cp16(unsigned dst, const void* src) {
    asm volatile("cp.async.cg.shared.global [%0], [%1], 16;" :: "r"(dst), "l"(src));
}

// ---------------- K0: scaled W_proj copy; fold W_k into queries; reset accumulators ----------------
__global__ void k0_precompute(const float* __restrict__ lq,
                              const float* __restrict__ W_k,
                              const float* __restrict__ b_k,
                              const float* __restrict__ W_proj) {
    int t = threadIdx.x;
    int gidx = blockIdx.x * 256 + t;
    if (gidx < IN_DIM * DD) g_Bp[gidx] = W_proj[gidx] * BSCALE;

    if (blockIdx.x == 0) {
        {
            int d = t >> 2, q = t & 3;
            float s = 0.f;
            #pragma unroll
            for (int j = 0; j < DD; j++) s = fmaf(W_k[d * DD + j], lq[q * DD + j], s);
            g_Wq[d * NQ + q] = s;
        }
        if (t < NQ) {
            float s = 0.f;
            #pragma unroll
            for (int j = 0; j < DD; j++) s = fmaf(lq[t * DD + j], b_k[j], s);
            g_c[t] = s;
            g_sum[t] = 0.f;
        }
        g_latent[t] = 0.f;
        if (t == 0) g_ticket = 0u;
    }
}

// ---------------- K1: tf32 MMA GEMM (4-stage cp.async, raw-fp32 operands) + fused epilogue ----------------
__global__ __launch_bounds__(THREADS, 2)
void k1_mma(const float* __restrict__ patch,
            const float* __restrict__ bp, const float* __restrict__ Wg,
            const float* __restrict__ bg, const unsigned char* __restrict__ mask,
            float* __restrict__ out_scores) {
    extern __shared__ float smem[];
    float* As = smem + AS_OFF;
    float* Bs = smem + BS_OFF;
    float* xs = smem + XS_OFF;
    __shared__ float psum[NQ];

    const int tid = threadIdx.x;
    const int lane = tid & 31;
    const int wid = tid >> 5;
    const int wm = wid & 3;             // row slice 0..3
    const int wn = wid >> 2;            // col slice 0..1
    const int g = lane >> 2;            // 0..7
    const int t = lane & 3;             // 0..3
    const int block_row = blockIdx.x * BR;

    if (tid < NQ) psum[tid] = 0.f;

    const unsigned smem_base = (unsigned)__cvta_generic_to_shared(smem);
    const unsigned as_base = smem_base + AS_OFF * 4;
    const unsigned bs_base = smem_base + BS_OFF * 4;

    // per-thread cp.async indices
    const int a_row0 = tid >> 2;           // chunk tid      -> rows 0..63
    const int a_row1 = (tid + 256) >> 2;   // chunk tid+256  -> rows 64..127
    const int a_c = tid & 3;               // 16B chunk within row
    const int b_k = tid >> 4;
    const int b_c = tid & 15;
    const size_t a_src0 = (size_t)min(block_row + a_row0, N_ROWS - 1) * IN_DIM + a_c * 4;
    const size_t a_src1 = (size_t)min(block_row + a_row1, N_ROWS - 1) * IN_DIM + a_c * 4;

    float acc[2][4][4];
    #pragma unroll
    for (int mt = 0; mt < 2; mt++)
        #pragma unroll
        for (int nt = 0; nt < 4; nt++)
            #pragma unroll
            for (int i = 0; i < 4; i++) acc[mt][nt][i] = 0.f;

    const int NTILES = IN_DIM / KT;  // 64

    // prologue: stages 0..2
    #pragma unroll
    for (int s = 0; s < STAGES - 1; s++) {
        int kt = s * KT;
        cp16(as_base + (s * AS_STAGE + a_row0 * AS_STRIDE + a_c * 4) * 4, patch + a_src0 + kt);
        cp16(as_base + (s * AS_STAGE + a_row1 * AS_STRIDE + a_c * 4) * 4, patch + a_src1 + kt);
        cp16(bs_base + (s * BS_STAGE + b_k * BS_STRIDE + b_c * 4) * 4,
             g_Bp + (size_t)(kt + b_k) * DD + b_c * 4);
        asm volatile("cp.async.commit_group;");
    }

    for (int it = 0; it < NTILES; it++) {
        asm volatile("cp.async.wait_group 2;");
        __syncthreads();

        if (it + STAGES - 1 < NTILES) {
            int s = (it + STAGES - 1) & (STAGES - 1);
            int kt = (it + STAGES - 1) * KT;
            cp16(as_base + (s * AS_STAGE + a_row0 * AS_STRIDE + a_c * 4) * 4, patch + a_src0 + kt);
            cp16(as_base + (s * AS_STAGE + a_row1 * AS_STRIDE + a_c * 4) * 4, patch + a_src1 + kt);
            cp16(bs_base + (s * BS_STAGE + b_k * BS_STRIDE + b_c * 4) * 4,
                 g_Bp + (size_t)(kt + b_k) * DD + b_c * 4);
        }
        asm volatile("cp.async.commit_group;");

        const float* Ab = As + (it & (STAGES - 1)) * AS_STAGE;
        const float* Bb = Bs + (it & (STAGES - 1)) * BS_STAGE;

        #pragma unroll
        for (int ks = 0; ks < 2; ks++) {
            const int kb = ks * 8;
            unsigned a[2][4];
            #pragma unroll
            for (int mt = 0; mt < 2; mt++) {
                int r0 = wm * 32 + mt * 16;
                a[mt][0] = __float_as_uint(Ab[(r0 + g) * AS_STRIDE + kb + t]);
                a[mt][1] = __float_as_uint(Ab[(r0 + g + 8) * AS_STRIDE + kb + t]);
                a[mt][2] = __float_as_uint(Ab[(r0 + g) * AS_STRIDE + kb + t + 4]);
                a[mt][3] = __float_as_uint(Ab[(r0 + g + 8) * AS_STRIDE + kb + t + 4]);
            }
            unsigned b[4][2];
            #pragma unroll
            for (int nt = 0; nt < 4; nt++) {
                int c0 = wn * 32 + nt * 8;
                b[nt][0] = __float_as_uint(Bb[(kb + t) * BS_STRIDE + c0 + g]);
                b[nt][1] = __float_as_uint(Bb[(kb + t + 4) * BS_STRIDE + c0 + g]);
            }
            #pragma unroll
            for (int mt = 0; mt < 2; mt++)
                #pragma unroll
                for (int nt = 0; nt < 4; nt++)
                    mma_tf32(acc[mt][nt], a[mt], b[nt]);
        }
    }

    // store x tile: registers -> smem staging + global scratch (with bias)
    #pragma unroll
    for (int mt = 0; mt < 2; mt++) {
        #pragma unroll
        for (int nt = 0; nt < 4; nt++) {
            int col = wn * 32 + nt * 8 + t * 2;
            float b0 = bp[col], b1 = bp[col + 1];
            int lrow = wm * 32 + mt * 16 + g;
            int row = block_row + lrow;
            float v0 = acc[mt][nt][0] + b0, v1 = acc[mt][nt][1] + b1;
            xs[lrow * XS_STRIDE + col] = v0;
            xs[lrow * XS_STRIDE + col + 1] = v1;
            if (row < N_ROWS)
                *(float2*)(g_x + (size_t)row * DD + col) = make_float2(v0, v1);
            float v2 = acc[mt][nt][2] + b0, v3 = acc[mt][nt][3] + b1;
            xs[(lrow + 8) * XS_STRIDE + col] = v2;
            xs[(lrow + 8) * XS_STRIDE + col + 1] = v3;
            if (row + 8 < N_ROWS)
                *(float2*)(g_x + (size_t)(row + 8) * DD + col) = make_float2(v2, v3);
        }
    }
    __syncthreads();

    // fused epilogue: gate + 4 scores + exp weights + partial softmax sums
    if (tid < BR) {
        int grow = block_row + tid;
        bool in_range = (grow < N_ROWS);
        float zg = bg[0];
        float dq[4] = {g_c[0], g_c[1], g_c[2], g_c[3]};
        const float* xr = xs + tid * XS_STRIDE;
        #pragma unroll
        for (int d = 0; d < DD; d++) {
            float xv = xr[d];
            zg = fmaf(xv, Wg[d], zg);
            #pragma unroll
            for (int q = 0; q < NQ; q++)
                dq[q] = fmaf(xv, g_Wq[d * NQ + q], dq[q]);
        }
        float gate = 1.f / (1.f + expf(-zg));
        float gs = gate * 0.125f;                 // scale = 1/sqrt(64)
        bool valid = in_range && (mask[min(grow, N_ROWS - 1)] == 0);
        float w[4];
        #pragma unroll
        for (int q = 0; q < NQ; q++) {
            float s = gs * dq[q];
            if (in_range) out_scores[(size_t)q * N_ROWS + grow] = s;
            w[q] = valid ? expf(s) : 0.f;          // softmax shift-invariant; scores O(1)
            if (in_range) g_w[(size_t)q * N_ROWS + grow] = w[q];
        }
        // warp-level reduce of w before shared atomics
        #pragma unroll
        for (int q = 0; q < NQ; q++) {
            float v = w[q];
            #pragma unroll
            for (int off = 16; off > 0; off >>= 1)
                v += __shfl_xor_sync(0xffffffffu, v, off);
            if (lane == 0) atomicAdd(&psum[q], v);
        }
    }
    __syncthreads();
    if (tid < NQ) atomicAdd(&g_sum[tid], psum[tid]);
}

// ---------------- K3: latent reduction + (last block) final FC -> logits ----------------
// grid = 1250 -> each block handles exactly 80 rows; 4 groups of 64 threads, 20 iters each
__global__ void k3_latent(const float* __restrict__ W_fc, const float* __restrict__ b_fc,
                          const float* __restrict__ W_out, const float* __restrict__ b_out,
                          float* __restrict__ logits) {
    const int tid = threadIdx.x;       // 256
    const int d = tid & 63;
    const int g = tid >> 6;            // 0..3 row-groups
    const int n0 = blockIdx.x * 80;

    float acc[NQ] = {0.f, 0.f, 0.f, 0.f};
    #pragma unroll
    for (int i = 0; i < 20; i++) {
        int n = n0 + g + i * 4;
        float xv = g_x[(size_t)n * DD + d];
        #pragma unroll
        for (int q = 0; q < NQ; q++)
            acc[q] = fmaf(__ldg(&g_w[(size_t)q * N_ROWS + n]), xv, acc[q]);
    }
    __shared__ float red[4][NQ][DD];
    #pragma unroll
    for (int q = 0; q < NQ; q++) red[g][q][d] = acc[q];
    __syncthreads();
    if (g == 0) {
        #pragma unroll
        for (int q = 0; q < NQ; q++) {
            float s = red[0][q][d] + red[1][q][d] + red[2][q][d] + red[3][q][d];
            atomicAdd(&g_latent[q * DD + d], s / g_sum[q]);
        }
    }

    // ---- last-block does the final MLP ----
    __threadfence();
    __shared__ unsigned is_last;
    if (tid == 0) is_last = (atomicAdd(&g_ticket, 1u) == (unsigned)(gridDim.x - 1));
    __syncthreads();
    if (!is_last) return;

    __shared__ float v[NQ * DD];
    __shared__ float hpart[4][DD];
    __shared__ float h[DD];
    v[tid] = g_latent[tid];
    __syncthreads();
    {
        float s = 0.f;
        const float* wp = W_fc + (size_t)(g * 64) * DD + d;
        const float* vp = v + g * 64;
        #pragma unroll 8
        for (int i = 0; i < 64; i++)
            s = fmaf(vp[i], wp[(size_t)i * DD], s);
        hpart[g][d] = s;
    }
    __syncthreads();
    if (tid < DD) {
        float s = hpart[0][tid] + hpart[1][tid] + hpart[2][tid] + hpart[3][tid] + b_fc[tid];
        h[tid] = fmaxf(s, 0.f);
    }
    __syncthreads();
    if (tid < OUT_DIM) {
        float s = b_out[tid];
        #pragma unroll
        for (int j = 0; j < DD; j++)
            s = fmaf(h[j], W_out[j * OUT_DIM + tid], s);
        logits[tid] = s;
    }
}

extern "C" void kernel_launch(void* const* d_in, const int* in_sizes, int n_in,
                              void* d_out, int out_size) {
    const float*         patch  = (const float*)d_in[0];
    const unsigned char* mask   = (const unsigned char*)d_in[1];
    const float*         lq     = (const float*)d_in[2];
    const float*         W_proj = (const float*)d_in[3];
    const float*         b_proj = (const float*)d_in[4];
    const float*         W_k    = (const float*)d_in[5];
    const float*         b_k    = (const float*)d_in[6];
    const float*         W_gate = (const float*)d_in[7];
    const float*         b_gate = (const float*)d_in[8];
    const float*         W_fc   = (const float*)d_in[9];
    const float*         b_fc   = (const float*)d_in[10];
    const float*         W_out  = (const float*)d_in[11];
    const float*         b_out  = (const float*)d_in[12];

    float* out     = (float*)d_out;
    float* logits  = out;          // 4 floats
    float* scores  = out + 4;      // A_out: [4, 100000]

    cudaFuncSetAttribute(k1_mma, cudaFuncAttributeMaxDynamicSharedMemorySize, SMEM_BYTES);

    k0_precompute<<<(IN_DIM * DD + 255) / 256, 256>>>(lq, W_k, b_k, W_proj);
    k1_mma<<<(N_ROWS + BR - 1) / BR, THREADS, SMEM_BYTES>>>(patch, b_proj,
                                                            W_gate, b_gate, mask, scores);
    k3_latent<<<K3_BLOCKS, 256>>>(W_fc, b_fc, W_out, b_out, logits);
}

// round 10
// speedup vs baseline: 3.2534x; 1.1459x over previous
#include <cuda_runtime.h>
#include <cuda_fp16.h>
#include <math.h>
#include <stdint.h>

#define N_ROWS 100000
#define IN_DIM 1024
#define DD 64
#define NQ 4
#define OUT_DIM 4

#define BR 128
#define KT 16
#define NTILES (IN_DIM / KT)    // 64
#define THREADS 256
#define STAGES 4

// ---- dynamic smem layout (bytes) ----
#define AS_STRIDE 24                        // floats per A row (16 data + 8 pad) -> conflict-free float2
#define A_STAGE_B (BR * AS_STRIDE * 4)      // 12288
#define BS_STRIDE 24
#define B_STAGE_B (DD * BS_STRIDE * 4)      // 6144
#define A_OFF 0
#define B_OFF (STAGES * A_STAGE_B)          // 49152
#define AUX_OFF (B_OFF + STAGES * B_STAGE_B)// 73728
#define PSUM_OFF  (AUX_OFF)                 // 4 floats
#define BPS_OFF   (AUX_OFF + 64)            // 64 floats
#define WGS_OFF   (BPS_OFF + 256)           // 64 floats
#define WQS_OFF   (WGS_OFF + 256)           // 256 floats
#define CQ_OFF    (WQS_OFF + 1024)          // 4 floats
#define BG_OFF    (CQ_OFF + 16)
#define SMEM_BYTES (AUX_OFF + 2048)         // 75776

#define XS_STRIDE 65                        // xs overlays A stages 0-2 post-mainloop (33280 < 36864)

#define K3_BLOCKS 1250

// Scratch (no allocations allowed -> device globals)
__device__ float g_x[(size_t)N_ROWS * DD];
__device__ float g_w[(size_t)NQ * N_ROWS];
__device__ float g_sum[NQ];
__device__ float g_latent[NQ * DD];
__device__ float g_Wq[DD * NQ];                  // W_k @ latent_q^T, [d][q]
__device__ float g_c[NQ];                        // latent_q . b_k
__device__ float g_WT[(size_t)DD * IN_DIM];      // W_proj^T, [n][k]
__device__ unsigned g_ticket;

// ---- helpers ----
__device__ __forceinline__ void cp16(unsigned dst, const void* src) {
    asm volatile("cp.async.cg.shared.global [%0], [%1], 16;" :: "r"(dst), "l"(src));
}

__device__ __forceinline__ unsigned packh2(float2 v) {
    __half2 h = __floats2half2_rn(v.x, v.y);   // .x -> low half (k even), .y -> high (k odd)
    return *(unsigned*)&h;
}

__device__ __forceinline__ void mma_f16(float* c, const unsigned* a, const unsigned* b) {
    asm volatile(
        "mma.sync.aligned.m16n8k16.row.col.f32.f16.f16.f32 "
        "{%0,%1,%2,%3}, {%4,%5,%6,%7}, {%8,%9}, {%0,%1,%2,%3};"
        : "+f"(c[0]), "+f"(c[1]), "+f"(c[2]), "+f"(c[3])
        : "r"(a[0]), "r"(a[1]), "r"(a[2]), "r"(a[3]),
          "r"(b[0]), "r"(b[1]));
}

// ---------------- K0: transpose W_proj -> g_WT [n][k]; fold W_k; reset accumulators ----------------
__global__ void k0_precompute(const float* __restrict__ lq,
                              const float* __restrict__ W_k,
                              const float* __restrict__ b_k,
                              const float* __restrict__ W_proj) {
    __shared__ float tile[64][65];
    const int t = threadIdx.x;
    const int b = blockIdx.x;          // 16 blocks; block b -> k rows [b*64, b*64+64)

    #pragma unroll
    for (int j = 0; j < 16; j++) {
        int idx = t + j * 256;
        int kk = idx >> 6, n = idx & 63;
        tile[kk][n] = W_proj[(size_t)(b * 64 + kk) * DD + n];
    }
    __syncthreads();
    #pragma unroll
    for (int j = 0; j < 16; j++) {
        int idx = t + j * 256;
        int n = idx >> 6, kk = idx & 63;
        g_WT[(size_t)n * IN_DIM + b * 64 + kk] = tile[kk][n];
    }

    if (b == 0) {
        {
            int d = t >> 2, q = t & 3;
            float s = 0.f;
            #pragma unroll
            for (int j = 0; j < DD; j++) s = fmaf(W_k[d * DD + j], lq[q * DD + j], s);
            g_Wq[d * NQ + q] = s;
        }
        if (t < NQ) {
            float s = 0.f;
            #pragma unroll
            for (int j = 0; j < DD; j++) s = fmaf(lq[t * DD + j], b_k[j], s);
            g_c[t] = s;
            g_sum[t] = 0.f;
        }
        g_latent[t] = 0.f;
        if (t == 0) g_ticket = 0u;
    }
}

__device__ __forceinline__ void load_stage(const float* __restrict__ patch, int block_row,
                                           int tid, unsigned sbase, int s, int kt) {
    #pragma unroll
    for (int j = 0; j < 2; j++) {
        int chunk = tid + j * 256;
        int row = chunk >> 2, c = chunk & 3;
        const float* src = patch + (size_t)min(block_row + row, N_ROWS - 1) * IN_DIM + kt + c * 4;
        cp16(sbase + A_OFF + s * A_STAGE_B + row * (AS_STRIDE * 4) + c * 16, src);
    }
    {
        int n = tid >> 2, c = tid & 3;
        const float* src = g_WT + (size_t)n * IN_DIM + kt + c * 4;
        cp16(sbase + B_OFF + s * B_STAGE_B + n * (BS_STRIDE * 4) + c * 16, src);
    }
}

// ---------------- K1: fp16 m16n8k16 MMA GEMM (4-stage cp.async) + fused epilogue ----------------
__global__ __launch_bounds__(THREADS, 2)
void k1_mma(const float* __restrict__ patch,
            const float* __restrict__ bp, const float* __restrict__ Wg,
            const float* __restrict__ bg, const unsigned char* __restrict__ mask,
            float* __restrict__ out_scores) {
    extern __shared__ char smem[];
    const unsigned sbase = (unsigned)__cvta_generic_to_shared(smem);
    float* xs   = (float*)smem;                   // overlay of A stages (safe post-mainloop)
    float* psum = (float*)(smem + PSUM_OFF);
    float* bps  = (float*)(smem + BPS_OFF);
    float* wgs  = (float*)(smem + WGS_OFF);
    float* wqs  = (float*)(smem + WQS_OFF);
    float* cqs  = (float*)(smem + CQ_OFF);
    float* bgs  = (float*)(smem + BG_OFF);

    const int tid = threadIdx.x;
    const int lane = tid & 31;
    const int wid = tid >> 5;
    const int wm = wid & 3;             // row slice 0..3
    const int wn = wid >> 2;            // col slice 0..1
    const int g = lane >> 2;            // 0..7
    const int t = lane & 3;             // 0..3
    const int block_row = blockIdx.x * BR;

    if (tid < DD) { bps[tid] = bp[tid]; wgs[tid] = Wg[tid]; }
    if (tid < DD * NQ) wqs[tid] = g_Wq[tid];
    if (tid < NQ) { cqs[tid] = g_c[tid]; psum[tid] = 0.f; }
    if (tid == 0) bgs[0] = bg[0];

    float acc[2][4][4];
    #pragma unroll
    for (int mt = 0; mt < 2; mt++)
        #pragma unroll
        for (int nt = 0; nt < 4; nt++)
            #pragma unroll
            for (int i = 0; i < 4; i++) acc[mt][nt][i] = 0.f;

    // prologue: stages 0..2
    #pragma unroll
    for (int s = 0; s < STAGES - 1; s++) {
        load_stage(patch, block_row, tid, sbase, s, s * KT);
        asm volatile("cp.async.commit_group;");
    }

    for (int it = 0; it < NTILES; it++) {
        asm volatile("cp.async.wait_group 2;");
        __syncthreads();

        if (it + STAGES - 1 < NTILES)
            load_stage(patch, block_row, tid, sbase, (it + 3) & 3, (it + 3) * KT);
        asm volatile("cp.async.commit_group;");

        const float* Ab = (const float*)(smem + A_OFF + (it & 3) * A_STAGE_B);
        const float* Bb = (const float*)(smem + B_OFF + (it & 3) * B_STAGE_B);

        unsigned a[2][4];
        #pragma unroll
        for (int mt = 0; mt < 2; mt++) {
            int r0 = wm * 32 + mt * 16;
            float2 v0 = *(const float2*)(Ab + (r0 + g) * AS_STRIDE + 2 * t);
            float2 v1 = *(const float2*)(Ab + (r0 + g + 8) * AS_STRIDE + 2 * t);
            float2 v2 = *(const float2*)(Ab + (r0 + g) * AS_STRIDE + 2 * t + 8);
            float2 v3 = *(const float2*)(Ab + (r0 + g + 8) * AS_STRIDE + 2 * t + 8);
            a[mt][0] = packh2(v0); a[mt][1] = packh2(v1);
            a[mt][2] = packh2(v2); a[mt][3] = packh2(v3);
        }
        unsigned b[4][2];
        #pragma unroll
        for (int nt = 0; nt < 4; nt++) {
            int c0 = wn * 32 + nt * 8;
            float2 w0 = *(const float2*)(Bb + (c0 + g) * BS_STRIDE + 2 * t);
            float2 w1 = *(const float2*)(Bb + (c0 + g) * BS_STRIDE + 2 * t + 8);
            b[nt][0] = packh2(w0); b[nt][1] = packh2(w1);
        }
        #pragma unroll
        for (int mt = 0; mt < 2; mt++)
            #pragma unroll
            for (int nt = 0; nt < 4; nt++)
                mma_f16(acc[mt][nt], a[mt], b[nt]);
    }
    __syncthreads();   // all warps done with smem stages before xs overlay writes

    // store x tile: registers -> smem staging (xs overlays A stages) + global scratch
    #pragma unroll
    for (int mt = 0; mt < 2; mt++) {
        #pragma unroll
        for (int nt = 0; nt < 4; nt++) {
            int col = wn * 32 + nt * 8 + t * 2;
            float b0 = bps[col], b1 = bps[col + 1];
            int lrow = wm * 32 + mt * 16 + g;
            int row = block_row + lrow;
            float v0 = acc[mt][nt][0] + b0, v1 = acc[mt][nt][1] + b1;
            xs[lrow * XS_STRIDE + col] = v0;
            xs[lrow * XS_STRIDE + col + 1] = v1;
            if (row < N_ROWS)
                *(float2*)(g_x + (size_t)row * DD + col) = make_float2(v0, v1);
            float v2 = acc[mt][nt][2] + b0, v3 = acc[mt][nt][3] + b1;
            xs[(lrow + 8) * XS_STRIDE + col] = v2;
            xs[(lrow + 8) * XS_STRIDE + col + 1] = v3;
            if (row + 8 < N_ROWS)
                *(float2*)(g_x + (size_t)(row + 8) * DD + col) = make_float2(v2, v3);
        }
    }
    __syncthreads();

    // fused epilogue: gate + 4 scores + exp weights + partial softmax sums
    if (tid < BR) {
        int grow = block_row + tid;
        bool in_range = (grow < N_ROWS);
        float zg = bgs[0];
        float dq[4] = {cqs[0], cqs[1], cqs[2], cqs[3]};
        const float* xr = xs + tid * XS_STRIDE;
        #pragma unroll
        for (int d = 0; d < DD; d++) {
            float xv = xr[d];
            zg = fmaf(xv, wgs[d], zg);
            #pragma unroll
            for (int q = 0; q < NQ; q++)
                dq[q] = fmaf(xv, wqs[d * NQ + q], dq[q]);
        }
        float gate = 1.f / (1.f + expf(-zg));
        float gs = gate * 0.125f;                 // 1/sqrt(64)
        bool valid = in_range && (mask[min(grow, N_ROWS - 1)] == 0);
        float w[4];
        #pragma unroll
        for (int q = 0; q < NQ; q++) {
            float s = gs * dq[q];
            if (in_range) out_scores[(size_t)q * N_ROWS + grow] = s;
            w[q] = valid ? expf(s) : 0.f;          // softmax shift-invariant; scores O(1)
            if (in_range) g_w[(size_t)q * N_ROWS + grow] = w[q];
        }
        #pragma unroll
        for (int q = 0; q < NQ; q++) {
            float v = w[q];
            #pragma unroll
            for (int off = 16; off > 0; off >>= 1)
                v += __shfl_xor_sync(0xffffffffu, v, off);
            if (lane == 0) atomicAdd(&psum[q], v);
        }
    }
    __syncthreads();
    if (tid < NQ) atomicAdd(&g_sum[tid], psum[tid]);
}

// ---------------- K3: latent reduction + (last block) final FC -> logits ----------------
__global__ void k3_latent(const float* __restrict__ W_fc, const float* __restrict__ b_fc,
                          const float* __restrict__ W_out, const float* __restrict__ b_out,
                          float* __restrict__ logits) {
    const int tid = threadIdx.x;       // 256
    const int d = tid & 63;
    const int g = tid >> 6;            // 0..3 row-groups
    const int n0 = blockIdx.x * 80;

    float acc[NQ] = {0.f, 0.f, 0.f, 0.f};
    #pragma unroll
    for (int i = 0; i < 20; i++) {
        int n = n0 + g + i * 4;
        float xv = g_x[(size_t)n * DD + d];
        #pragma unroll
        for (int q = 0; q < NQ; q++)
            acc[q] = fmaf(__ldg(&g_w[(size_t)q * N_ROWS + n]), xv, acc[q]);
    }
    __shared__ float red[4][NQ][DD];
    #pragma unroll
    for (int q = 0; q < NQ; q++) red[g][q][d] = acc[q];
    __syncthreads();
    if (g == 0) {
        #pragma unroll
        for (int q = 0; q < NQ; q++) {
            float s = red[0][q][d] + red[1][q][d] + red[2][q][d] + red[3][q][d];
            atomicAdd(&g_latent[q * DD + d], s / g_sum[q]);
        }
    }

    // ---- last-block does the final MLP ----
    __threadfence();
    __shared__ unsigned is_last;
    if (tid == 0) is_last = (atomicAdd(&g_ticket, 1u) == (unsigned)(gridDim.x - 1));
    __syncthreads();
    if (!is_last) return;

    __shared__ float v[NQ * DD];
    __shared__ float hpart[4][DD];
    __shared__ float h[DD];
    v[tid] = g_latent[tid];
    __syncthreads();
    {
        float s = 0.f;
        const float* wp = W_fc + (size_t)(g * 64) * DD + d;
        const float* vp = v + g * 64;
        #pragma unroll 8
        for (int i = 0; i < 64; i++)
            s = fmaf(vp[i], wp[(size_t)i * DD], s);
        hpart[g][d] = s;
    }
    __syncthreads();
    if (tid < DD) {
        float s = hpart[0][tid] + hpart[1][tid] + hpart[2][tid] + hpart[3][tid] + b_fc[tid];
        h[tid] = fmaxf(s, 0.f);
    }
    __syncthreads();
    if (tid < OUT_DIM) {
        float s = b_out[tid];
        #pragma unroll
        for (int j = 0; j < DD; j++)
            s = fmaf(h[j], W_out[j * OUT_DIM + tid], s);
        logits[tid] = s;
    }
}

extern "C" void kernel_launch(void* const* d_in, const int* in_sizes, int n_in,
                              void* d_out, int out_size) {
    const float*         patch  = (const float*)d_in[0];
    const unsigned char* mask   = (const unsigned char*)d_in[1];
    const float*         lq     = (const float*)d_in[2];
    const float*         W_proj = (const float*)d_in[3];
    const float*         b_proj = (const float*)d_in[4];
    const float*         W_k    = (const float*)d_in[5];
    const float*         b_k    = (const float*)d_in[6];
    const float*         W_gate = (const float*)d_in[7];
    const float*         b_gate = (const float*)d_in[8];
    const float*         W_fc   = (const float*)d_in[9];
    const float*         b_fc   = (const float*)d_in[10];
    const float*         W_out  = (const float*)d_in[11];
    const float*         b_out  = (const float*)d_in[12];

    float* out     = (float*)d_out;
    float* logits  = out;          // 4 floats
    float* scores  = out + 4;      // A_out: [4, 100000]

    cudaFuncSetAttribute(k1_mma, cudaFuncAttributeMaxDynamicSharedMemorySize, SMEM_BYTES);

    k0_precompute<<<16, 256>>>(lq, W_k, b_k, W_proj);
    k1_mma<<<(N_ROWS + BR - 1) / BR, THREADS, SMEM_BYTES>>>(patch, b_proj,
                                                            W_gate, b_gate, mask, scores);
    k3_latent<<<K3_BLOCKS, 256>>>(W_fc, b_fc, W_out, b_out, logits);
}